// round 17
// baseline (speedup 1.0000x reference)
#include <cuda_runtime.h>
#include <cuda_fp16.h>
#include <math.h>
#include <stdint.h>

#define S_DIM 2048
#define B_DIM 4
#define H_DIM 1024
#define NHEAD 16
#define DHEAD 64
#define M_DIM (S_DIM * B_DIM)   // 8192

// fp16 inputs (persistent scratch)
__device__ __half g_Xh[(size_t)M_DIM * H_DIM];
__device__ __half g_Wh[3][(size_t)H_DIM * H_DIM];
// Projected q,k,v in fp16: [M, H]
__device__ __half g_q[(size_t)M_DIM * H_DIM];
__device__ __half g_k[(size_t)M_DIM * H_DIM];
__device__ __half g_v[(size_t)M_DIM * H_DIM];

extern __shared__ __half dynsm[];

// ---------------------------------------------------------------------------
// helpers
// ---------------------------------------------------------------------------
__device__ __forceinline__ uint32_t sma(const void* p) {
    return (uint32_t)__cvta_generic_to_shared(p);
}
__device__ __forceinline__ void ldm4(uint32_t r[4], uint32_t a) {
    asm volatile("ldmatrix.sync.aligned.m8n8.x4.shared.b16 {%0,%1,%2,%3},[%4];"
                 : "=r"(r[0]), "=r"(r[1]), "=r"(r[2]), "=r"(r[3]) : "r"(a));
}
__device__ __forceinline__ void ldm4t(uint32_t r[4], uint32_t a) {
    asm volatile("ldmatrix.sync.aligned.m8n8.x4.trans.shared.b16 {%0,%1,%2,%3},[%4];"
                 : "=r"(r[0]), "=r"(r[1]), "=r"(r[2]), "=r"(r[3]) : "r"(a));
}
__device__ __forceinline__ void mma16(float c[4], const uint32_t a[4],
                                      uint32_t b0, uint32_t b1) {
    asm volatile("mma.sync.aligned.m16n8k16.row.col.f32.f16.f16.f32 "
                 "{%0,%1,%2,%3},{%4,%5,%6,%7},{%8,%9},{%0,%1,%2,%3};"
                 : "+f"(c[0]), "+f"(c[1]), "+f"(c[2]), "+f"(c[3])
                 : "r"(a[0]), "r"(a[1]), "r"(a[2]), "r"(a[3]), "r"(b0), "r"(b1));
}
__device__ __forceinline__ uint32_t h2u(__half2 h) {
    return *reinterpret_cast<uint32_t*>(&h);
}
__device__ __forceinline__ uint32_t h2exp2(uint32_t x) {
    uint32_t r;
    asm("ex2.approx.f16x2 %0, %1;" : "=r"(r) : "r"(x));
    return r;
}
__device__ __forceinline__ void cpa16(uint32_t dst, const void* src) {
    asm volatile("cp.async.cg.shared.global [%0], [%1], 16;" :: "r"(dst), "l"(src));
}
__device__ __forceinline__ void cpa4(uint32_t dst, const void* src) {
    asm volatile("cp.async.ca.shared.global [%0], [%1], 4;" :: "r"(dst), "l"(src));
}
__device__ __forceinline__ void cp_commit() {
    asm volatile("cp.async.commit_group;");
}
template <int N>
__device__ __forceinline__ void cp_wait() {
    asm volatile("cp.async.wait_group %0;" :: "n"(N));
}

// ---------------------------------------------------------------------------
// Fused convert pre-pass (single launch; identical to R15).
// ---------------------------------------------------------------------------
#define NX4 ((int)((size_t)M_DIM * H_DIM / 4))   // 2097152
#define NW4 ((int)((size_t)H_DIM * H_DIM / 4))   // 262144
#define NTOT4 (NX4 + 3 * NW4)                    // 2883584

__global__ __launch_bounds__(256) void to_half_all(
    const float* __restrict__ X,
    const float* __restrict__ Wq, const float* __restrict__ Wk,
    const float* __restrict__ Wv)
{
    int i = blockIdx.x * blockDim.x + threadIdx.x;
    if (i >= NTOT4) return;
    const float* src;
    __half* dst;
    int j = i;
    if (j < NX4) {
        src = X;   dst = g_Xh;
    } else if ((j -= NX4) < NW4) {
        src = Wq;  dst = g_Wh[0];
    } else if ((j -= NW4) < NW4) {
        src = Wk;  dst = g_Wh[1];
    } else {
        j -= NW4;
        src = Wv;  dst = g_Wh[2];
    }
    float4 v = ((const float4*)src)[j];
    ((uint2*)dst)[j] = make_uint2(
        h2u(__floats2half2_rn(v.x, v.y)), h2u(__floats2half2_rn(v.z, v.w)));
}

// ---------------------------------------------------------------------------
// Single-pass fp16 QKV GEMM (identical to R7).
// CTA 128x128, BK=32, 256 threads, 3-stage cp.async pipeline.
// ---------------------------------------------------------------------------
#define Q_STRIDE 40
#define Q_BUF_H  (128 * Q_STRIDE)        // 5120 halfs
#define Q_BUF_B  (Q_BUF_H * 2)           // 10240 bytes
#define Q_STAGE_B (2 * Q_BUF_B)          // 20480 bytes
#define Q_NSTAGE 3

__global__ __launch_bounds__(256) void qkv_gemm_v3(
    const float* __restrict__ bq, const float* __restrict__ bk,
    const float* __restrict__ bv)
{
    const int which = blockIdx.z;
    const float* bias = (which == 0) ? bq : (which == 1) ? bk : bv;
    __half* out       = (which == 0) ? g_q : (which == 1) ? g_k : g_v;
    const __half* Xh = g_Xh;
    const __half* Wh = g_Wh[which];

    const int tid  = threadIdx.x;
    const int lane = tid & 31, warp = tid >> 5;
    const int g = lane >> 2, t = lane & 3;
    const int wm = warp & 3, wn = warp >> 2;
    const int m0 = blockIdx.y * 128, n0 = blockIdx.x * 128;

    const uint32_t SB = sma(dynsm);

    const int asel = lane & 15, ablk = (lane >> 4) * 8;
    const int br = lane & 7, bs = lane >> 3;
    const uint32_t aA_off = (uint32_t)(((wm * 32 + asel) * Q_STRIDE + ablk) * 2);
    const uint32_t bB_off = (uint32_t)(Q_BUF_B +
        ((wn * 64 + br + (bs >> 1) * 8) * Q_STRIDE + (bs & 1) * 8) * 2);

    int prow[2], pcol[2];
#pragma unroll
    for (int j = 0; j < 2; j++) {
        int c = tid + j * 256;
        prow[j] = c >> 2;
        pcol[j] = (c & 3) * 8;
    }

    auto prefetch = [&](int stage, int k0) {
        const uint32_t st = SB + stage * Q_STAGE_B;
#pragma unroll
        for (int j = 0; j < 2; j++) {
            const uint32_t doff = (uint32_t)((prow[j] * Q_STRIDE + pcol[j]) * 2);
            cpa16(st + doff,
                  Xh + (size_t)(m0 + prow[j]) * H_DIM + k0 + pcol[j]);
            cpa16(st + Q_BUF_B + doff,
                  Wh + (size_t)(n0 + prow[j]) * H_DIM + k0 + pcol[j]);
        }
        cp_commit();
    };

    float acc[2][8][4];
#pragma unroll
    for (int i = 0; i < 2; i++)
#pragma unroll
        for (int j = 0; j < 8; j++)
#pragma unroll
            for (int r = 0; r < 4; r++) acc[i][j][r] = 0.f;

    prefetch(0, 0);
    prefetch(1, 32);
    prefetch(2, 64);

    const int NT = H_DIM / 32;   // 32 k-tiles
#pragma unroll 1
    for (int kt = 0; kt < NT; kt++) {
        cp_wait<Q_NSTAGE - 1>();
        __syncthreads();

        const int p = kt % Q_NSTAGE;
        const uint32_t st  = SB + p * Q_STAGE_B;
        const uint32_t aXp = st + aA_off;
        const uint32_t bWp = st + bB_off;

#pragma unroll
        for (int kc = 0; kc < 2; kc++) {
            uint32_t ah[2][4];
#pragma unroll
            for (int mt = 0; mt < 2; mt++)
                ldm4(ah[mt], aXp + (uint32_t)((mt * 16 * Q_STRIDE + kc * 16) * 2));
#pragma unroll
            for (int ntp = 0; ntp < 4; ntp++) {
                uint32_t bh[4];
                ldm4(bh, bWp + (uint32_t)((ntp * 16 * Q_STRIDE + kc * 16) * 2));
#pragma unroll
                for (int hn = 0; hn < 2; hn++) {
                    const int nt = 2 * ntp + hn;
#pragma unroll
                    for (int mt = 0; mt < 2; mt++)
                        mma16(acc[mt][nt], ah[mt], bh[2 * hn], bh[2 * hn + 1]);
                }
            }
        }
        __syncthreads();
        if (kt + Q_NSTAGE < NT) prefetch(p, (kt + Q_NSTAGE) * 32);
        else                    cp_commit();
    }

#pragma unroll
    for (int nt = 0; nt < 8; nt++) {
        const int col = n0 + wn * 64 + nt * 8 + 2 * t;
        const float b0 = bias[col], b1 = bias[col + 1];
#pragma unroll
        for (int mt = 0; mt < 2; mt++) {
            const int r0 = m0 + wm * 32 + mt * 16 + g;
            *(__half2*)(out + (size_t)r0 * H_DIM + col) =
                __floats2half2_rn(acc[mt][nt][0] + b0, acc[mt][nt][1] + b1);
            *(__half2*)(out + (size_t)(r0 + 8) * H_DIM + col) =
                __floats2half2_rn(acc[mt][nt][2] + b0, acc[mt][nt][3] + b1);
        }
    }
}

// ---------------------------------------------------------------------------
// Flash attention v9: chunked dataflow + f16x2 exponentials.
// Q pre-scaled by 0.125*log2(e) -> QK mma emits log2-domain scores.
// P = ex2.approx.f16x2(score + (mask-4)*log2e): one MUFU per 2 elements,
// output half2 is directly the PV A-fragment. l accumulated from the same
// fp16 P values the PV mma consumes.
// ---------------------------------------------------------------------------
#define A_STRIDE 72
#define A_KV_H   (64 * A_STRIDE)
#define A_STAGE_H (2 * A_KV_H)
#define A_MASK_H (2 * A_STAGE_H)

__global__ __launch_bounds__(256, 2) void attn_fp16_v9(const float* __restrict__ mask,
                                                       float* __restrict__ out)
{
    float* maskv = (float*)(dynsm + A_MASK_H);   // [2][64]

    const int tid  = threadIdx.x;
    const int lane = tid & 31, warp = tid >> 5;
    const int g = lane >> 2, t = lane & 3;
    const int head = blockIdx.y, b = head >> 4, h = head & 15;
    const int s0 = blockIdx.x * 128;

    const size_t rs   = (size_t)B_DIM * H_DIM;
    const size_t base = (size_t)b * H_DIM + h * DHEAD;

    const uint32_t SB = sma(dynsm);

    const int asel = lane & 15, ablk = (lane >> 4) * 8;
    const int br = lane & 7, bs = lane >> 3;
    const uint32_t aQ = SB + (uint32_t)(((warp * 16 + asel) * A_STRIDE + ablk) * 2);
    const uint32_t bK_off =
        (uint32_t)(((br + (bs >> 1) * 8) * A_STRIDE + (bs & 1) * 8) * 2);
    const uint32_t bV_off =
        (uint32_t)(((br + (bs & 1) * 8) * A_STRIDE + (bs >> 1) * 8) * 2);

    int prow[2], pcol[2];
#pragma unroll
    for (int j = 0; j < 2; j++) {
        int c = tid + j * 256;
        prow[j] = c >> 3;
        pcol[j] = (c & 7) * 8;
    }
    const __half* kg = g_k + base;
    const __half* vg = g_v + base;
    const float*  mg = mask + (size_t)b * S_DIM;

    auto prefetch = [&](int stage, int t0) {
        const uint32_t st = SB + (uint32_t)(stage * A_STAGE_H * 2);
#pragma unroll
        for (int j = 0; j < 2; j++) {
            const uint32_t doff = (uint32_t)((prow[j] * A_STRIDE + pcol[j]) * 2);
            cpa16(st + doff,               kg + (size_t)(t0 + prow[j]) * rs + pcol[j]);
            cpa16(st + A_KV_H * 2 + doff,  vg + (size_t)(t0 + prow[j]) * rs + pcol[j]);
        }
        if (tid < 64)
            cpa4(SB + (uint32_t)(A_MASK_H * 2 + (stage * 64 + tid) * 4), mg + t0 + tid);
        cp_commit();
    };

    // ---- stage Q through stage-0 K/V region (prologue only) ----
    {
        const int qlr = tid >> 1, qlc = (tid & 1) * 32;
        const __half* qp = g_q + base + (size_t)(s0 + qlr) * rs + qlc;
#pragma unroll
        for (int u = 0; u < 4; u++)
            *(uint4*)&dynsm[qlr * A_STRIDE + qlc + 8 * u] = *(const uint4*)(qp + 8 * u);
    }
    __syncthreads();
    uint32_t qf[4][4];
    // scale = 1/8 * log2(e): scores come out of the mma in log2 domain
    const __half2 s2 = __floats2half2_rn(0.18033688f, 0.18033688f);
#pragma unroll
    for (int ks = 0; ks < 4; ks++) {
        ldm4(qf[ks], aQ + (uint32_t)(ks * 16 * 2));
#pragma unroll
        for (int r = 0; r < 4; r++) {
            __half2 v = *reinterpret_cast<__half2*>(&qf[ks][r]);
            v = __hmul2(v, s2);
            qf[ks][r] = h2u(v);
        }
    }
    __syncthreads();   // Q consumed; stage-0 buffer free for the pipeline

    prefetch(0, 0);
    prefetch(1, 64);

    float l0 = 0.f, l1 = 0.f;        // per-thread partial row sums
    float oacc[8][4];
#pragma unroll
    for (int j = 0; j < 8; j++)
#pragma unroll
        for (int r = 0; r < 4; r++) oacc[j][r] = 0.f;

    const int NT = S_DIM / 64;
    const float L2E  = 1.44269504f;
    const float MOFF = -4.0f * 1.44269504f;   // (mask-4)*log2e, mask part via FMA

#pragma unroll 1
    for (int it = 0; it < NT; it++) {
        if (it < NT - 1) cp_wait<1>(); else cp_wait<0>();
        __syncthreads();

        const int p = it & 1;
        const uint32_t st = SB + (uint32_t)(p * A_STAGE_H * 2);
        const uint32_t bK = st + bK_off;
        const uint32_t bV = st + A_KV_H * 2 + bV_off;
        const float* mvp = maskv + p * 64;

        // ---- per 16-key chunk: QK -> ex2(f16x2) -> PV ----
#pragma unroll
        for (int kc = 0; kc < 4; kc++) {
            float s0a[4], s1a[4];
#pragma unroll
            for (int r = 0; r < 4; r++) { s0a[r] = 0.f; s1a[r] = 0.f; }
#pragma unroll
            for (int ks = 0; ks < 4; ks++) {
                uint32_t bf[4];
                ldm4(bf, bK + (uint32_t)((kc * 16 * A_STRIDE + ks * 16) * 2));
                mma16(s0a, qf[ks], bf[0], bf[1]);
                mma16(s1a, qf[ks], bf[2], bf[3]);
            }

            // log2-domain mask offsets
            const float mvA0 = fmaf(mvp[kc * 16 + 2 * t],     L2E, MOFF);
            const float mvA1 = fmaf(mvp[kc * 16 + 2 * t + 1], L2E, MOFF);
            const float mvB0 = fmaf(mvp[kc * 16 + 8 + 2 * t],     L2E, MOFF);
            const float mvB1 = fmaf(mvp[kc * 16 + 8 + 2 * t + 1], L2E, MOFF);

            // pack log2 scores to half2, exponentiate pairwise
            uint32_t af[4];
            af[0] = h2exp2(h2u(__floats2half2_rn(s0a[0] + mvA0, s0a[1] + mvA1)));
            af[1] = h2exp2(h2u(__floats2half2_rn(s0a[2] + mvA0, s0a[3] + mvA1)));
            af[2] = h2exp2(h2u(__floats2half2_rn(s1a[0] + mvB0, s1a[1] + mvB1)));
            af[3] = h2exp2(h2u(__floats2half2_rn(s1a[2] + mvB0, s1a[3] + mvB1)));

            // l from the same fp16 P the PV mma consumes
            float2 f0 = __half22float2(*reinterpret_cast<__half2*>(&af[0]));
            float2 f1 = __half22float2(*reinterpret_cast<__half2*>(&af[1]));
            float2 f2 = __half22float2(*reinterpret_cast<__half2*>(&af[2]));
            float2 f3 = __half22float2(*reinterpret_cast<__half2*>(&af[3]));
            l0 += f0.x + f0.y + f2.x + f2.y;
            l1 += f1.x + f1.y + f3.x + f3.y;

            // PV chunk kc
#pragma unroll
            for (int ntp = 0; ntp < 4; ntp++) {
                uint32_t bf[4];
                ldm4t(bf, bV + (uint32_t)((kc * 16 * A_STRIDE + ntp * 16) * 2));
                mma16(oacc[2 * ntp],     af, bf[0], bf[1]);
                mma16(oacc[2 * ntp + 1], af, bf[2], bf[3]);
            }
        }
        __syncthreads();
        if (it + 2 < NT) prefetch(p, (it + 2) * 64);
    }

    // ---- epilogue: reduce l across the quad once, normalize, store ----
    l0 += __shfl_xor_sync(0xffffffffu, l0, 1);
    l0 += __shfl_xor_sync(0xffffffffu, l0, 2);
    l1 += __shfl_xor_sync(0xffffffffu, l1, 1);
    l1 += __shfl_xor_sync(0xffffffffu, l1, 2);
    const float inv0 = 1.f / l0, inv1 = 1.f / l1;
    float* op = out + (size_t)(s0 + warp * 16) * rs + base;
#pragma unroll
    for (int nt = 0; nt < 8; nt++) {
        *(float2*)(op + (size_t)g * rs + nt * 8 + 2 * t) =
            make_float2(oacc[nt][0] * inv0, oacc[nt][1] * inv0);
        *(float2*)(op + (size_t)(g + 8) * rs + nt * 8 + 2 * t) =
            make_float2(oacc[nt][2] * inv1, oacc[nt][3] * inv1);
    }
}

// ---------------------------------------------------------------------------
extern "C" void kernel_launch(void* const* d_in, const int* in_sizes, int n_in,
                              void* d_out, int out_size)
{
    const float* X    = (const float*)d_in[0];
    const float* mask = (const float*)d_in[1];
    const float* Wq   = (const float*)d_in[2];
    const float* bq   = (const float*)d_in[3];
    const float* Wk   = (const float*)d_in[4];
    const float* bk   = (const float*)d_in[5];
    const float* Wv   = (const float*)d_in[6];
    const float* bv   = (const float*)d_in[7];
    float* out = (float*)d_out;

    // fused convert pre-pass (single launch)
    to_half_all<<<(NTOT4 + 255) / 256, 256>>>(X, Wq, Wk, Wv);

    // QKV GEMM (single-pass fp16, 3-stage pipeline — R7 config)
    const int q_smem = Q_NSTAGE * Q_STAGE_B;   // 61440
    cudaFuncSetAttribute(qkv_gemm_v3, cudaFuncAttributeMaxDynamicSharedMemorySize,
                         q_smem);
    dim3 ggrid(H_DIM / 128, M_DIM / 128, 3);   // (8, 64, 3)
    qkv_gemm_v3<<<ggrid, 256, q_smem>>>(bq, bk, bv);

    // attention v9 (chunked dataflow + f16x2 ex2)
    const int a_smem = (A_MASK_H * 2) + 2 * 64 * (int)sizeof(float);  // 37376
    cudaFuncSetAttribute(attn_fp16_v9, cudaFuncAttributeMaxDynamicSharedMemorySize,
                         a_smem);
    dim3 agrid(S_DIM / 128, B_DIM * NHEAD);    // (16, 64)
    attn_fp16_v9<<<agrid, 256, a_smem>>>(mask, out);
}